// round 8
// baseline (speedup 1.0000x reference)
#include <cuda_runtime.h>
#include <cuda_bf16.h>
#include <cstdint>

// Router: logits = x @ W^T via split-bf16 mma.sync (3 terms), fused softmax/top-2.
// W pre-converted to bf16 hi/lo once per launch; B staged via cp.async;
// A conversion interleaved into the MMA phase.
// Outputs concatenated fp32: mask[T*64] | idx[T*2] | router_probs[T*64] | probs[T*64]

#define THREADS 128
#define TM 64             // tokens per CTA
#define CK 64             // K chunk
#define NCH (2048 / CK)   // 32
#define ASTR 144          // smem row stride bytes (64 bf16 = 128B + 16 pad)

// per-buffer smem layout (bytes): A hi/lo 64 rows, B hi/lo 64 rows
#define AHI_O 0
#define ALO_O 9216        // 64*144
#define BHI_O 18432
#define BLO_O 27648
#define BUFSZ 36864
#define SMEMB (2 * BUFSZ)
#define LS 68             // logits row stride (floats)

typedef unsigned long long ull;

__device__ __nv_bfloat16 g_Whi[64 * 2048];
__device__ __nv_bfloat16 g_Wlo[64 * 2048];

__device__ __forceinline__ uint32_t smem_u32(const void* p) {
    uint32_t a;
    asm("{ .reg .u64 t; cvta.to.shared.u64 t, %1; cvt.u32.u64 %0, t; }"
        : "=r"(a) : "l"(p));
    return a;
}

__device__ __forceinline__ void ldm4(uint32_t* r, uint32_t addr) {
    asm volatile("ldmatrix.sync.aligned.m8n8.x4.shared.b16 {%0,%1,%2,%3}, [%4];"
        : "=r"(r[0]), "=r"(r[1]), "=r"(r[2]), "=r"(r[3]) : "r"(addr));
}

// non-volatile: pure register op, lets ptxas schedule across STS/cp.async
__device__ __forceinline__ void mma16816(float* d, const uint32_t* a,
                                         uint32_t b0, uint32_t b1) {
    asm("mma.sync.aligned.m16n8k16.row.col.f32.bf16.bf16.f32 "
        "{%0,%1,%2,%3}, {%4,%5,%6,%7}, {%8,%9}, {%0,%1,%2,%3};"
        : "+f"(d[0]), "+f"(d[1]), "+f"(d[2]), "+f"(d[3])
        : "r"(a[0]), "r"(a[1]), "r"(a[2]), "r"(a[3]), "r"(b0), "r"(b1));
}

// fp32x4 -> bf16 hi x4 (8B) + bf16 lo x4 (8B)
__device__ __forceinline__ void split4(float4 v, ull& H, ull& L) {
    uint32_t hu0, hu1;
    asm("cvt.rn.bf16x2.f32 %0, %1, %2;" : "=r"(hu0) : "f"(v.y), "f"(v.x));
    asm("cvt.rn.bf16x2.f32 %0, %1, %2;" : "=r"(hu1) : "f"(v.w), "f"(v.z));
    const float h0 = __uint_as_float(hu0 << 16);
    const float h1 = __uint_as_float(hu0 & 0xffff0000u);
    const float h2 = __uint_as_float(hu1 << 16);
    const float h3 = __uint_as_float(hu1 & 0xffff0000u);
    uint32_t gu0, gu1;
    asm("cvt.rn.bf16x2.f32 %0, %1, %2;" : "=r"(gu0) : "f"(v.y - h1), "f"(v.x - h0));
    asm("cvt.rn.bf16x2.f32 %0, %1, %2;" : "=r"(gu1) : "f"(v.w - h3), "f"(v.z - h2));
    asm("mov.b64 %0, {%1, %2};" : "=l"(H) : "r"(hu0), "r"(hu1));
    asm("mov.b64 %0, {%1, %2};" : "=l"(L) : "r"(gu0), "r"(gu1));
}

__device__ __forceinline__ void cvt_store(uint32_t hi_addr, uint32_t lo_addr, float4 v) {
    ull H, L;
    split4(v, H, L);
    asm volatile("st.shared.b64 [%0], %1;" :: "r"(hi_addr), "l"(H) : "memory");
    asm volatile("st.shared.b64 [%0], %1;" :: "r"(lo_addr), "l"(L) : "memory");
}

__device__ __forceinline__ void cpa16(uint32_t dst, const void* src) {
    asm volatile("cp.async.cg.shared.global [%0], [%1], 16;"
                 :: "r"(dst), "l"(src) : "memory");
}

// ---- pre-kernel: convert W (64x2048 fp32) -> bf16 hi/lo ----
__global__ void __launch_bounds__(256)
wprep_kernel(const float* __restrict__ W)
{
    const int i = blockIdx.x * 256 + threadIdx.x;   // 0..32767 float4s
    const float4 v = reinterpret_cast<const float4*>(W)[i];
    ull H, L;
    split4(v, H, L);
    reinterpret_cast<ull*>(g_Whi)[i] = H;
    reinterpret_cast<ull*>(g_Wlo)[i] = L;
}

__global__ void __launch_bounds__(THREADS, 2)
router_kernel(const float* __restrict__ x, float* __restrict__ out, int T)
{
    extern __shared__ __align__(128) char dsm[];
    const uint32_t sb = smem_u32(dsm);

    const int tid = threadIdx.x;
    const int wid = tid >> 5;
    const int lane = tid & 31;
    const int row0 = blockIdx.x * TM;

    float4 ax[8];
    float d[8][4];
#pragma unroll
    for (int t = 0; t < 8; t++)
#pragma unroll
        for (int j = 0; j < 4; j++) d[t][j] = 0.f;

    // per-thread B cp.async coords
    const int brr = tid >> 3 << 0;   // unused placeholder removed below

    // ---- prologue: chunk 0 ----
    {
#pragma unroll
        for (int i = 0; i < 4; i++) {
            const int f = i * THREADS + tid;     // 0..511
            const int rr = f >> 3;               // 0..63
            const int cc = f & 7;
            const uint32_t o = (uint32_t)(rr * ASTR + cc * 16);
            cpa16(sb + BHI_O + o, g_Whi + (size_t)rr * 2048 + cc * 8);
            cpa16(sb + BLO_O + o, g_Wlo + (size_t)rr * 2048 + cc * 8);
        }
        asm volatile("cp.async.commit_group;" ::: "memory");
#pragma unroll
        for (int i = 0; i < 8; i++) {
            const int f = i * THREADS + tid;     // 0..1023
            const int grow = row0 + (f >> 4);
            ax[i] = (grow < T)
                ? *reinterpret_cast<const float4*>(x + (size_t)grow * 2048 + (f & 15) * 4)
                : make_float4(0.f, 0.f, 0.f, 0.f);
        }
#pragma unroll
        for (int i = 0; i < 8; i++) {
            const int f = i * THREADS + tid;
            const uint32_t o = (uint32_t)((f >> 4) * ASTR + (f & 15) * 8);
            cvt_store(sb + AHI_O + o, sb + ALO_O + o, ax[i]);
        }
        asm volatile("cp.async.wait_group 0;" ::: "memory");
    }
    __syncthreads();

    // ldmatrix per-lane offsets
    const uint32_t a_off = (uint32_t)((wid * 16 + (lane & 15)) * ASTR + ((lane >> 4) << 4));
    const uint32_t b_off = (uint32_t)((((lane & 7) + ((lane >> 4) & 1) * 8)) * ASTR
                                      + (((lane >> 3) & 1) << 4));

    for (int c = 0; c < NCH; c++) {
        const uint32_t cur = sb + (uint32_t)(c & 1) * BUFSZ;
        const uint32_t nxt = sb + (uint32_t)((c + 1) & 1) * BUFSZ;
        const bool more = (c + 1 < NCH);

        if (more) {
            const int k0 = (c + 1) * CK;
            // B: async copy straight into next buffer (no registers)
#pragma unroll
            for (int i = 0; i < 4; i++) {
                const int f = i * THREADS + tid;
                const int rr = f >> 3;
                const int cc = f & 7;
                const uint32_t o = (uint32_t)(rr * ASTR + cc * 16);
                cpa16(nxt + BHI_O + o, g_Whi + (size_t)rr * 2048 + k0 + cc * 8);
                cpa16(nxt + BLO_O + o, g_Wlo + (size_t)rr * 2048 + k0 + cc * 8);
            }
            asm volatile("cp.async.commit_group;" ::: "memory");
            // A: global prefetch into registers
#pragma unroll
            for (int i = 0; i < 8; i++) {
                const int f = i * THREADS + tid;
                const int grow = row0 + (f >> 4);
                if (grow < T)
                    ax[i] = *reinterpret_cast<const float4*>(
                        x + (size_t)grow * 2048 + k0 + (f & 15) * 4);
            }
        }

        // ---- MMA phase with A-convert interleaved at kk=1..3 ----
#pragma unroll
        for (int kk = 0; kk < 4; kk++) {
            const uint32_t ko = kk * 32;  // 16 bf16 = 32 bytes
            uint32_t ah[4], al[4];
            ldm4(ah, cur + AHI_O + a_off + ko);
            ldm4(al, cur + ALO_O + a_off + ko);
#pragma unroll
            for (int j = 0; j < 4; j++) {
                uint32_t vh[4], vl[4];
                const uint32_t bo = (uint32_t)(j * 16 * ASTR) + b_off + ko;
                ldm4(vh, cur + BHI_O + bo);
                ldm4(vl, cur + BLO_O + bo);
#pragma unroll
                for (int tt = 0; tt < 2; tt++) {
                    float* dd = d[j * 2 + tt];
                    mma16816(dd, ah, vh[tt * 2], vh[tt * 2 + 1]);
                    mma16816(dd, ah, vl[tt * 2], vl[tt * 2 + 1]);
                    mma16816(dd, al, vh[tt * 2], vh[tt * 2 + 1]);
                }
            }
            if (more && kk > 0) {
                const int base = (kk - 1) * 3;        // 0,3,6
                const int cnt = (kk == 3) ? 2 : 3;
#pragma unroll
                for (int u = 0; u < 3; u++) {
                    if (u < cnt) {
                        const int i = base + u;
                        const int f = i * THREADS + tid;
                        const uint32_t o = (uint32_t)((f >> 4) * ASTR + (f & 15) * 8);
                        cvt_store(nxt + AHI_O + o, nxt + ALO_O + o, ax[i]);
                    }
                }
            }
        }

        if (more) asm volatile("cp.async.wait_group 0;" ::: "memory");
        __syncthreads();
    }

    // ---- dump logits to smem [TM][LS] ----
    float* lg = reinterpret_cast<float*>(dsm);
    {
        const int r1 = wid * 16 + (lane >> 2);   // 0..63
        const int n0 = (lane & 3) * 2;
#pragma unroll
        for (int t = 0; t < 8; t++) {
            *reinterpret_cast<float2*>(lg + r1 * LS + t * 8 + n0) =
                make_float2(d[t][0], d[t][1]);
            *reinterpret_cast<float2*>(lg + (r1 + 8) * LS + t * 8 + n0) =
                make_float2(d[t][2], d[t][3]);
        }
    }
    __syncthreads();

    // ---- epilogue: one thread = one token (threads 0..63) ----
    if (tid >= TM) return;
    const int row = row0 + tid;
    if (row >= T) return;

    float l[64];
#pragma unroll
    for (int e = 0; e < 64; e += 4) {
        const float4 v = *reinterpret_cast<const float4*>(lg + tid * LS + e);
        l[e] = v.x; l[e + 1] = v.y; l[e + 2] = v.z; l[e + 3] = v.w;
    }

    // top-2 (earliest index wins ties, matching lax.top_k)
    float m1 = -3.402823466e38f, m2 = -3.402823466e38f;
    int i1 = 0, i2 = 0;
#pragma unroll
    for (int e = 0; e < 64; e++) {
        const float v = l[e];
        if (v > m1) { m2 = m1; i2 = i1; m1 = v; i1 = e; }
        else if (v > m2) { m2 = v; i2 = e; }
    }

    float s = 0.f;
    float p[64];
#pragma unroll
    for (int e = 0; e < 64; e++) {
        p[e] = __expf(l[e] - m1);
        s += p[e];
    }
    const float inv = 1.0f / s;

    const float p1 = p[i1] * inv;
    const float p2 = p[i2] * inv;
    const float rs = 1.0f / (p1 + p2);

    const size_t Tz = (size_t)T;
    float* mask = out;
    float* idxo = out + Tz * 64;
    float* rp   = out + Tz * 64 + Tz * 2;
    float* pr   = out + Tz * 64 + Tz * 2 + Tz * 64;
    const size_t gt = (size_t)row;

#pragma unroll
    for (int e = 0; e < 64; e += 4) {
        float4 pv4, m4, r4;
        float* pvp = &pv4.x; float* mp = &m4.x; float* rpp = &r4.x;
#pragma unroll
        for (int j = 0; j < 4; j++) {
            const int ee = e + j;
            const float pv = p[ee] * inv;
            const bool sel = (ee == i1) | (ee == i2);
            pvp[j] = pv;
            mp[j] = sel ? 1.0f : 0.0f;
            rpp[j] = sel ? pv * rs : 0.0f;
        }
        *reinterpret_cast<float4*>(pr + gt * 64 + e) = pv4;
        *reinterpret_cast<float4*>(mask + gt * 64 + e) = m4;
        *reinterpret_cast<float4*>(rp + gt * 64 + e) = r4;
    }
    idxo[gt * 2 + 0] = (float)i1;
    idxo[gt * 2 + 1] = (float)i2;
}

extern "C" void kernel_launch(void* const* d_in, const int* in_sizes, int n_in,
                              void* d_out, int out_size)
{
    const float* x = (const float*)d_in[0];
    const float* W = (const float*)d_in[1];
    const int T = in_sizes[0] / 2048;

    wprep_kernel<<<128, 256>>>(W);

    cudaFuncSetAttribute(router_kernel,
                         cudaFuncAttributeMaxDynamicSharedMemorySize, SMEMB);
    const int blocks = (T + TM - 1) / TM;
    router_kernel<<<blocks, THREADS, SMEMB>>>(x, (float*)d_out, T);
}

// round 9
// speedup vs baseline: 1.1962x; 1.1962x over previous
#include <cuda_runtime.h>
#include <cuda_bf16.h>
#include <cstdint>

// Router: logits = x @ W^T via split-bf16 mma.sync (3 terms), warp-specialized
// producer/consumer pipeline. W pre-converted to bf16 hi/lo once per launch.
// Outputs concatenated fp32: mask[T*64] | idx[T*2] | router_probs[T*64] | probs[T*64]

#define THREADS 256       // warps 0-3 consumers, 4-7 producers
#define TM 64             // tokens per CTA
#define CK 64             // K chunk
#define NCH (2048 / CK)   // 32
#define ASTR 144          // smem row stride bytes (64 bf16 = 128B + 16 pad)

// per-buffer smem layout (bytes): A hi/lo 64 rows, B hi/lo 64 rows
#define AHI_O 0
#define ALO_O 9216        // 64*144
#define BHI_O 18432
#define BLO_O 27648
#define BUFSZ 36864
#define SMEMB (2 * BUFSZ)
#define LS 68             // logits row stride (floats)

typedef unsigned long long ull;

__device__ __nv_bfloat16 g_Whi[64 * 2048];
__device__ __nv_bfloat16 g_Wlo[64 * 2048];

#define BAR_SYNC(id)   asm volatile("bar.sync %0, 256;"   :: "r"(id) : "memory")
#define BAR_ARRIVE(id) asm volatile("bar.arrive %0, 256;" :: "r"(id) : "memory")

__device__ __forceinline__ uint32_t smem_u32(const void* p) {
    uint32_t a;
    asm("{ .reg .u64 t; cvta.to.shared.u64 t, %1; cvt.u32.u64 %0, t; }"
        : "=r"(a) : "l"(p));
    return a;
}

__device__ __forceinline__ void ldm4(uint32_t* r, uint32_t addr) {
    asm volatile("ldmatrix.sync.aligned.m8n8.x4.shared.b16 {%0,%1,%2,%3}, [%4];"
        : "=r"(r[0]), "=r"(r[1]), "=r"(r[2]), "=r"(r[3]) : "r"(addr));
}

// register-only, non-volatile: ptxas may schedule freely
__device__ __forceinline__ void mma16816(float* d, const uint32_t* a,
                                         uint32_t b0, uint32_t b1) {
    asm("mma.sync.aligned.m16n8k16.row.col.f32.bf16.bf16.f32 "
        "{%0,%1,%2,%3}, {%4,%5,%6,%7}, {%8,%9}, {%0,%1,%2,%3};"
        : "+f"(d[0]), "+f"(d[1]), "+f"(d[2]), "+f"(d[3])
        : "r"(a[0]), "r"(a[1]), "r"(a[2]), "r"(a[3]), "r"(b0), "r"(b1));
}

// fp32x4 -> bf16 hi x4 (8B) + bf16 lo x4 (8B)
__device__ __forceinline__ void split4(float4 v, ull& H, ull& L) {
    uint32_t hu0, hu1;
    asm("cvt.rn.bf16x2.f32 %0, %1, %2;" : "=r"(hu0) : "f"(v.y), "f"(v.x));
    asm("cvt.rn.bf16x2.f32 %0, %1, %2;" : "=r"(hu1) : "f"(v.w), "f"(v.z));
    const float h0 = __uint_as_float(hu0 << 16);
    const float h1 = __uint_as_float(hu0 & 0xffff0000u);
    const float h2 = __uint_as_float(hu1 << 16);
    const float h3 = __uint_as_float(hu1 & 0xffff0000u);
    uint32_t gu0, gu1;
    asm("cvt.rn.bf16x2.f32 %0, %1, %2;" : "=r"(gu0) : "f"(v.y - h1), "f"(v.x - h0));
    asm("cvt.rn.bf16x2.f32 %0, %1, %2;" : "=r"(gu1) : "f"(v.w - h3), "f"(v.z - h2));
    asm("mov.b64 %0, {%1, %2};" : "=l"(H) : "r"(hu0), "r"(hu1));
    asm("mov.b64 %0, {%1, %2};" : "=l"(L) : "r"(gu0), "r"(gu1));
}

__device__ __forceinline__ void cvt_store(uint32_t hi_addr, uint32_t lo_addr, float4 v) {
    ull H, L;
    split4(v, H, L);
    asm volatile("st.shared.b64 [%0], %1;" :: "r"(hi_addr), "l"(H) : "memory");
    asm volatile("st.shared.b64 [%0], %1;" :: "r"(lo_addr), "l"(L) : "memory");
}

// ---- pre-kernel: convert W (64x2048 fp32) -> bf16 hi/lo ----
__global__ void __launch_bounds__(256)
wprep_kernel(const float* __restrict__ W)
{
    const int i = blockIdx.x * 256 + threadIdx.x;   // 0..32767 float4s
    const float4 v = reinterpret_cast<const float4*>(W)[i];
    ull H, L;
    split4(v, H, L);
    reinterpret_cast<ull*>(g_Whi)[i] = H;
    reinterpret_cast<ull*>(g_Wlo)[i] = L;
}

__global__ void __launch_bounds__(THREADS, 2)
router_kernel(const float* __restrict__ x, float* __restrict__ out, int T)
{
    extern __shared__ __align__(128) char dsm[];
    const uint32_t sb = smem_u32(dsm);

    const int tid = threadIdx.x;
    const int wid = tid >> 5;
    const int lane = tid & 31;
    const int row0 = blockIdx.x * TM;

    // barrier ids: full0=1, full1=2, empty0=3, empty1=4
    float d[8][4];
#pragma unroll
    for (int t = 0; t < 8; t++)
#pragma unroll
        for (int j = 0; j < 4; j++) d[t][j] = 0.f;

    if (wid >= 4) {
        // ================= PRODUCER (warps 4-7) =================
        const int tp = tid - 128;   // 0..127
        float4 ax[8];
        uint4 bh[4], bl[4];

        // load chunk 0
#pragma unroll
        for (int i = 0; i < 8; i++) {
            const int f = i * 128 + tp;
            const int grow = row0 + (f >> 4);
            ax[i] = (grow < T)
                ? *reinterpret_cast<const float4*>(x + (size_t)grow * 2048 + (f & 15) * 4)
                : make_float4(0.f, 0.f, 0.f, 0.f);
        }
#pragma unroll
        for (int i = 0; i < 4; i++) {
            const int f = i * 128 + tp;
            const int rr = f >> 3;
            const int cc = f & 7;
            bh[i] = *reinterpret_cast<const uint4*>(g_Whi + (size_t)rr * 2048 + cc * 8);
            bl[i] = *reinterpret_cast<const uint4*>(g_Wlo + (size_t)rr * 2048 + cc * 8);
        }

        for (int c = 0; c < NCH; c++) {
            const int b = c & 1;
            const uint32_t tb = sb + (uint32_t)b * BUFSZ;

            if (c >= 2) BAR_SYNC(3 + b);   // wait consumer freed this buffer

            // store staged chunk c
#pragma unroll
            for (int i = 0; i < 8; i++) {
                const int f = i * 128 + tp;
                const uint32_t o = (uint32_t)((f >> 4) * ASTR + (f & 15) * 8);
                cvt_store(tb + AHI_O + o, tb + ALO_O + o, ax[i]);
            }
#pragma unroll
            for (int i = 0; i < 4; i++) {
                const int f = i * 128 + tp;
                const uint32_t o = (uint32_t)((f >> 3) * ASTR + (f & 7) * 16);
                *reinterpret_cast<uint4*>(dsm + b * BUFSZ + BHI_O + o) = bh[i];
                *reinterpret_cast<uint4*>(dsm + b * BUFSZ + BLO_O + o) = bl[i];
            }
            asm volatile("membar.cta;" ::: "memory");
            BAR_ARRIVE(1 + b);             // buffer full

            // prefetch chunk c+1 (LDG latency hidden behind next empty wait)
            if (c + 1 < NCH) {
                const int k0 = (c + 1) * CK;
#pragma unroll
                for (int i = 0; i < 8; i++) {
                    const int f = i * 128 + tp;
                    const int grow = row0 + (f >> 4);
                    if (grow < T)
                        ax[i] = *reinterpret_cast<const float4*>(
                            x + (size_t)grow * 2048 + k0 + (f & 15) * 4);
                }
#pragma unroll
                for (int i = 0; i < 4; i++) {
                    const int f = i * 128 + tp;
                    const int rr = f >> 3;
                    const int cc = f & 7;
                    bh[i] = *reinterpret_cast<const uint4*>(
                        g_Whi + (size_t)rr * 2048 + k0 + cc * 8);
                    bl[i] = *reinterpret_cast<const uint4*>(
                        g_Wlo + (size_t)rr * 2048 + k0 + cc * 8);
                }
            }
        }
    } else {
        // ================= CONSUMER (warps 0-3) =================
        const uint32_t a_off = (uint32_t)((wid * 16 + (lane & 15)) * ASTR
                                          + ((lane >> 4) << 4));
        const uint32_t b_off = (uint32_t)((((lane & 7) + ((lane >> 4) & 1) * 8)) * ASTR
                                          + (((lane >> 3) & 1) << 4));

        for (int c = 0; c < NCH; c++) {
            const int b = c & 1;
            const uint32_t tb = sb + (uint32_t)b * BUFSZ;
            BAR_SYNC(1 + b);               // wait buffer full
#pragma unroll
            for (int kk = 0; kk < 4; kk++) {
                const uint32_t ko = kk * 32;
                uint32_t ah[4], al[4];
                ldm4(ah, tb + AHI_O + a_off + ko);
                ldm4(al, tb + ALO_O + a_off + ko);
#pragma unroll
                for (int j = 0; j < 4; j++) {
                    uint32_t vh[4], vl[4];
                    const uint32_t bo = (uint32_t)(j * 16 * ASTR) + b_off + ko;
                    ldm4(vh, tb + BHI_O + bo);
                    ldm4(vl, tb + BLO_O + bo);
#pragma unroll
                    for (int tt = 0; tt < 2; tt++) {
                        float* dd = d[j * 2 + tt];
                        mma16816(dd, ah, vh[tt * 2], vh[tt * 2 + 1]);
                        mma16816(dd, ah, vl[tt * 2], vl[tt * 2 + 1]);
                        mma16816(dd, al, vh[tt * 2], vh[tt * 2 + 1]);
                    }
                }
            }
            BAR_ARRIVE(3 + b);             // buffer free
        }
    }

    __syncthreads();

    // ---- dump logits to smem [TM][LS] (consumer warps only) ----
    float* lg = reinterpret_cast<float*>(dsm);
    if (wid < 4) {
        const int r1 = wid * 16 + (lane >> 2);   // 0..63
        const int n0 = (lane & 3) * 2;
#pragma unroll
        for (int t = 0; t < 8; t++) {
            *reinterpret_cast<float2*>(lg + r1 * LS + t * 8 + n0) =
                make_float2(d[t][0], d[t][1]);
            *reinterpret_cast<float2*>(lg + (r1 + 8) * LS + t * 8 + n0) =
                make_float2(d[t][2], d[t][3]);
        }
    }
    __syncthreads();

    // ---- epilogue: one thread = one token (threads 0..63) ----
    if (tid >= TM) return;
    const int row = row0 + tid;
    if (row >= T) return;

    float l[64];
#pragma unroll
    for (int e = 0; e < 64; e += 4) {
        const float4 v = *reinterpret_cast<const float4*>(lg + tid * LS + e);
        l[e] = v.x; l[e + 1] = v.y; l[e + 2] = v.z; l[e + 3] = v.w;
    }

    // top-2 (earliest index wins ties, matching lax.top_k)
    float m1 = -3.402823466e38f, m2 = -3.402823466e38f;
    int i1 = 0, i2 = 0;
#pragma unroll
    for (int e = 0; e < 64; e++) {
        const float v = l[e];
        if (v > m1) { m2 = m1; i2 = i1; m1 = v; i1 = e; }
        else if (v > m2) { m2 = v; i2 = e; }
    }

    float s = 0.f;
    float p[64];
#pragma unroll
    for (int e = 0; e < 64; e++) {
        p[e] = __expf(l[e] - m1);
        s += p[e];
    }
    const float inv = 1.0f / s;

    const float p1 = p[i1] * inv;
    const float p2 = p[i2] * inv;
    const float rs = 1.0f / (p1 + p2);

    const size_t Tz = (size_t)T;
    float* mask = out;
    float* idxo = out + Tz * 64;
    float* rp   = out + Tz * 64 + Tz * 2;
    float* pr   = out + Tz * 64 + Tz * 2 + Tz * 64;
    const size_t gt = (size_t)row;

#pragma unroll
    for (int e = 0; e < 64; e += 4) {
        float4 pv4, m4, r4;
        float* pvp = &pv4.x; float* mp = &m4.x; float* rpp = &r4.x;
#pragma unroll
        for (int j = 0; j < 4; j++) {
            const int ee = e + j;
            const float pv = p[ee] * inv;
            const bool sel = (ee == i1) | (ee == i2);
            pvp[j] = pv;
            mp[j] = sel ? 1.0f : 0.0f;
            rpp[j] = sel ? pv * rs : 0.0f;
        }
        *reinterpret_cast<float4*>(pr + gt * 64 + e) = pv4;
        *reinterpret_cast<float4*>(mask + gt * 64 + e) = m4;
        *reinterpret_cast<float4*>(rp + gt * 64 + e) = r4;
    }
    idxo[gt * 2 + 0] = (float)i1;
    idxo[gt * 2 + 1] = (float)i2;
}

extern "C" void kernel_launch(void* const* d_in, const int* in_sizes, int n_in,
                              void* d_out, int out_size)
{
    const float* x = (const float*)d_in[0];
    const float* W = (const float*)d_in[1];
    const int T = in_sizes[0] / 2048;

    wprep_kernel<<<128, 256>>>(W);

    cudaFuncSetAttribute(router_kernel,
                         cudaFuncAttributeMaxDynamicSharedMemorySize, SMEMB);
    const int blocks = (T + TM - 1) / TM;
    router_kernel<<<blocks, THREADS, SMEMB>>>(x, (float*)d_out, T);
}